// round 6
// baseline (speedup 1.0000x reference)
#include <cuda_runtime.h>
#include <cuda_fp16.h>
#include <math.h>
#include <stdint.h>

#define B_ 32
#define T_ 8
#define K_ 64
#define D_ 512
#define CIN_ 1536
#define HW_ 64
#define NT_ 256
#define RGRID 384

// ---------------- scratch (device globals; no allocation) ----------------
__device__ float g_xt [NT_ * D_ * HW_];   // (n, d, s)
__device__ float g_xtT[NT_ * HW_ * D_];   // (n, s, d)
__device__ __half g_xh[(size_t)NT_ * HW_ * CIN_];
__device__ __half g_wh[640 * CIN_];
__device__ float g_biasx[640];
__device__ float g_wxpb[NT_ * K_ * HW_];
__device__ float g_attv[NT_ * K_ * HW_];
__device__ float g_hs [T_ * B_ * K_ * HW_];
__device__ float g_h   [B_ * K_ * HW_];
__device__ float g_ah  [B_ * K_ * HW_];
__device__ float g_uz  [B_ * K_ * HW_];
__device__ float g_ur  [B_ * K_ * HW_];
__device__ float g_wxt0[B_ * K_ * HW_];
__device__ float g_wxtb[B_ * K_ * HW_];
__device__ float g_zb  [B_ * K_ * HW_];
__device__ float g_rh  [B_ * K_ * HW_];
__device__ float g_vlad[B_ * K_ * D_];
__device__ unsigned g_cnt = 0;
__device__ unsigned g_gen = 0;

__device__ __forceinline__ float sigmoidf_(float x) { return 1.f / (1.f + expf(-x)); }
__device__ __forceinline__ uint32_t smem_to_u32(const void* p) {
    uint32_t a;
    asm("{ .reg .u64 t; cvta.to.shared.u64 t, %1; cvt.u32.u64 %0, t; }"
        : "=r"(a) : "l"(p));
    return a;
}

// ---------------- grid barrier (all RGRID blocks co-resident) ----------------
__device__ __forceinline__ void gbar() {
    __syncthreads();
    if (threadIdx.x == 0) {
        __threadfence();
        unsigned gen = atomicAdd(&g_gen, 0u);
        unsigned t = atomicAdd(&g_cnt, 1u);
        if (t == RGRID - 1) {
            g_cnt = 0;
            __threadfence();
            atomicExch(&g_gen, gen + 1u);
        } else {
            volatile unsigned* vg = &g_gen;
            while (*vg == gen) { __nanosleep(64); }
            __threadfence();
        }
    }
    __syncthreads();
}

// ---------------- convert W to fp16 + zero pad rows 576-639 ----------------
__global__ void convert_w(const float* __restrict__ W) {
    int i = blockIdx.x * 1024 + threadIdx.x;
    if (i >= 640 * CIN_) return;
    int d = i / CIN_;
    if (d < 512) g_wh[i] = __float2half(W[i]);
    else if (d >= 576) g_wh[i] = __float2half(0.f);
}

// ---------------- wxW = w_x @ W (fp16 rows 512-575) + bias vector ----------
__global__ void __launch_bounds__(256) wxw_kernel(const float* __restrict__ redu_w,
                                                  const float* __restrict__ redu_b,
                                                  const float* __restrict__ wx) {
    __shared__ float sW[128 * 16];
    __shared__ float sX[64 * 128];
    int tid = threadIdx.x;
    int c0 = blockIdx.x * 16;
    int c_l = tid & 15, kq = tid >> 4;
    float acc[4] = {0.f, 0.f, 0.f, 0.f};
    for (int dc = 0; dc < 4; dc++) {
        __syncthreads();
        for (int i = tid; i < 2048; i += 256) {
            int dd = i >> 4, c = i & 15;
            sW[i] = redu_w[(size_t)(dc * 128 + dd) * CIN_ + c0 + c];
        }
        for (int i = tid; i < 8192; i += 256) {
            int k = i >> 7, dd = i & 127;
            sX[i] = wx[k * 512 + dc * 128 + dd];
        }
        __syncthreads();
        for (int dd = 0; dd < 128; dd++) {
            float wv = sW[dd * 16 + c_l];
#pragma unroll
            for (int i = 0; i < 4; i++)
                acc[i] += sX[(kq * 4 + i) * 128 + dd] * wv;
        }
    }
#pragma unroll
    for (int i = 0; i < 4; i++)
        g_wh[(size_t)(512 + kq * 4 + i) * CIN_ + c0 + c_l] = __float2half(acc[i]);

    if (blockIdx.x == 0) {
        if (tid < 256) {
            g_biasx[tid] = redu_b[tid];
            g_biasx[tid + 256] = redu_b[tid + 256];
        }
        if (tid < 64) {
            float s = 0.f;
            for (int d = 0; d < 512; d++) s += wx[tid * 512 + d] * redu_b[d];
            g_biasx[512 + tid] = s;
            g_biasx[576 + tid] = 0.f;
        }
    }
}

// ---------------- transpose x -> fp16 K-major ----------------
__global__ void __launch_bounds__(256) transpose_x(const float* __restrict__ x) {
    __shared__ float sm[64 * 65];
    int n = blockIdx.y, c0 = blockIdx.x * 64;
    const float* src = x + ((size_t)n * CIN_ + c0) * 64;
    for (int i = threadIdx.x; i < 4096; i += 256) {
        int ci = i >> 6, s = i & 63;
        sm[ci * 65 + s] = src[i];
    }
    __syncthreads();
#pragma unroll
    for (int rep = 0; rep < 8; rep++) {
        int idx = rep * 256 + threadIdx.x;
        int s = idx >> 5, cp = idx & 31, ci = cp * 2;
        __half2 h = __floats2half2_rn(sm[ci * 65 + s], sm[(ci + 1) * 65 + s]);
        *(__half2*)(g_xh + ((size_t)(n * 64 + s)) * CIN_ + c0 + ci) = h;
    }
}

// ============== HMMA GEMM, 3-stage cp.async pipeline ========================
#define EPAD 67
#define NCH 48
#define STG 20480
#define GSMEM (3 * STG)

__device__ __forceinline__ void mma16816(float* c, const uint32_t* a, const uint32_t* b) {
    asm volatile(
        "mma.sync.aligned.m16n8k16.row.col.f32.f16.f16.f32 "
        "{%0,%1,%2,%3}, {%4,%5,%6,%7}, {%8,%9}, {%0,%1,%2,%3};"
        : "+f"(c[0]), "+f"(c[1]), "+f"(c[2]), "+f"(c[3])
        : "r"(a[0]), "r"(a[1]), "r"(a[2]), "r"(a[3]), "r"(b[0]), "r"(b[1]));
}
#define LDSM4(r0, r1, r2, r3, addr) \
    asm volatile("ldmatrix.sync.aligned.m8n8.x4.shared.b16 {%0,%1,%2,%3}, [%4];" \
                 : "=r"(r0), "=r"(r1), "=r"(r2), "=r"(r3) : "r"(addr))
#define CPASYNC16(saddr, gptr) \
    asm volatile("cp.async.cg.shared.global [%0], [%1], 16;" :: "r"(saddr), "l"(gptr))
#define CPCOMMIT() asm volatile("cp.async.commit_group;")
#define CPWAIT(n)  asm volatile("cp.async.wait_group %0;" :: "n"(n))

__global__ void __launch_bounds__(256) gemm_redu_mma() {
    extern __shared__ __align__(16) char sbuf[];
    float* sEp = (float*)sbuf;
    uint32_t sb = smem_to_u32(sbuf);

    int tid = threadIdx.x;
    int wid = tid >> 5, lane = tid & 31;
    int warp_m = wid >> 2, warp_n = wid & 3;
    int moff = warp_m * 64, noff = warp_n * 32;
    int m0 = blockIdx.x * 128, n0 = blockIdx.y * 128;
    int lr = lane >> 2, lc = (lane & 3) * 2;

    float acc[4][4][4];
#pragma unroll
    for (int i = 0; i < 4; i++)
#pragma unroll
        for (int j = 0; j < 4; j++)
#pragma unroll
            for (int q = 0; q < 4; q++) acc[i][j][q] = 0.f;

    int lane16 = lane & 15, lanehi = lane >> 4;
    uint32_t aBase = sb + (uint32_t)((moff + lane16) * 80 + lanehi * 16);
    int bgrp = lane >> 3;
    int brow = (lane & 7) + ((bgrp >> 1) << 3);
    int bcol = (bgrp & 1) << 3;
    uint32_t bBase = sb + 10240 + (uint32_t)((noff + brow) * 80 + bcol * 2);

    auto load_chunk = [&](int st, int ch) {
        int k0 = ch * 32;
        uint32_t abuf = sb + st * STG, bbuf = abuf + 10240;
#pragma unroll
        for (int i = tid; i < 512; i += 256) {
            int r = i >> 2, c = i & 3;
            CPASYNC16(abuf + (uint32_t)(r * 80 + c * 16),
                      g_xh + (size_t)(m0 + r) * CIN_ + k0 + c * 8);
            CPASYNC16(bbuf + (uint32_t)(r * 80 + c * 16),
                      g_wh + (size_t)(n0 + r) * CIN_ + k0 + c * 8);
        }
    };

    load_chunk(0, 0);
    CPCOMMIT();
    load_chunk(1, 1);
    CPCOMMIT();

#pragma unroll 1
    for (int ch = 0; ch < NCH; ch++) {
        if (ch < NCH - 1) CPWAIT(1); else CPWAIT(0);
        __syncthreads();
        if (ch + 2 < NCH) {
            load_chunk((ch + 2) % 3, ch + 2);
            CPCOMMIT();
        }
        uint32_t stoff = (uint32_t)((ch % 3) * STG);
        uint32_t af[2][4][4], bf[2][4][2];
#pragma unroll
        for (int ks = 0; ks < 2; ks++) {
#pragma unroll
            for (int mf = 0; mf < 4; mf++)
                LDSM4(af[ks][mf][0], af[ks][mf][1], af[ks][mf][2], af[ks][mf][3],
                      aBase + stoff + (uint32_t)(mf * 16 * 80 + ks * 32));
#pragma unroll
            for (int nfp = 0; nfp < 2; nfp++)
                LDSM4(bf[ks][2 * nfp][0], bf[ks][2 * nfp][1],
                      bf[ks][2 * nfp + 1][0], bf[ks][2 * nfp + 1][1],
                      bBase + stoff + (uint32_t)(nfp * 16 * 80 + ks * 32));
        }
#pragma unroll
        for (int ks = 0; ks < 2; ks++)
#pragma unroll
            for (int mf = 0; mf < 4; mf++)
#pragma unroll
                for (int nf = 0; nf < 4; nf++)
                    mma16816(acc[mf][nf], af[ks][mf], bf[ks][nf]);
    }

    if (n0 < 512) {
#pragma unroll 1
        for (int slab = 0; slab < 2; slab++) {
            __syncthreads();
            if ((warp_n >> 1) == slab) {
                int ncol = (warp_n & 1) * 32;
#pragma unroll
                for (int mf = 0; mf < 4; mf++) {
                    int row = moff + mf * 16 + lr;
#pragma unroll
                    for (int nf = 0; nf < 4; nf++) {
                        int col = ncol + nf * 8 + lc;
                        sEp[row * EPAD + col]           = acc[mf][nf][0];
                        sEp[row * EPAD + col + 1]       = acc[mf][nf][1];
                        sEp[(row + 8) * EPAD + col]     = acc[mf][nf][2];
                        sEp[(row + 8) * EPAD + col + 1] = acc[mf][nf][3];
                    }
                }
            }
            __syncthreads();
            int dbase = n0 + slab * 64;
#pragma unroll
            for (int idx = tid; idx < 8192; idx += 256) {
                int m = idx & 127, dn = idx >> 7;
                int col = m0 + m, nn = col >> 6, ss = col & 63;
                int d = dbase + dn;
                g_xt[(size_t)nn * (D_ * HW_) + d * 64 + ss] = sEp[m * EPAD + dn] + g_biasx[d];
            }
#pragma unroll
            for (int idx = tid; idx < 8192; idx += 256) {
                int dn = idx & 63, m = idx >> 6;
                int col = m0 + m, nn = col >> 6, ss = col & 63;
                int d = dbase + dn;
                g_xtT[(size_t)nn * (HW_ * D_) + ss * 512 + d] = sEp[m * EPAD + dn] + g_biasx[d];
            }
        }
    } else {
        __syncthreads();
        if ((warp_n >> 1) == 0) {
            int ncol = (warp_n & 1) * 32;
#pragma unroll
            for (int mf = 0; mf < 4; mf++) {
                int row = moff + mf * 16 + lr;
#pragma unroll
                for (int nf = 0; nf < 4; nf++) {
                    int col = ncol + nf * 8 + lc;
                    sEp[row * EPAD + col]           = acc[mf][nf][0];
                    sEp[row * EPAD + col + 1]       = acc[mf][nf][1];
                    sEp[(row + 8) * EPAD + col]     = acc[mf][nf][2];
                    sEp[(row + 8) * EPAD + col + 1] = acc[mf][nf][3];
                }
            }
        }
        __syncthreads();
#pragma unroll
        for (int idx = tid; idx < 8192; idx += 256) {
            int m = idx & 127, dn = idx >> 7;
            int col = m0 + m, nn = col >> 6, ss = col & 63;
            g_wxpb[nn * 4096 + dn * 64 + ss] = sEp[m * EPAD + dn] + g_biasx[512 + dn];
        }
    }
}

// ============== conv3x3 core (128 thr, 16 oc, input via __ldcg) ==============
#define CPAD 96
#define WPAD 292

__device__ void conv3x3_v2(const float* __restrict__ gin,
                           const float* __restrict__ gw, int oc0,
                           float* sIn, float* sW, float acc[8]) {
    int tid = threadIdx.x;
    int y = tid & 7;
    int oc_l = tid >> 3;
    __syncthreads();   // protect sIn reuse across calls
    for (int i = tid; i < 4096; i += 128) {
        int ic = i >> 6, yy = (i >> 3) & 7, xx = i & 7;
        sIn[ic * CPAD + yy * 12 + xx] = __ldcg(&gin[i]);
    }
#pragma unroll
    for (int j = 0; j < 8; j++) acc[j] = 0.f;

#pragma unroll 1
    for (int half = 0; half < 2; half++) {
        __syncthreads();
        for (int i = tid; i < 4608; i += 128) {
            int oc = i / 288, icq = i - oc * 288;
            sW[oc * WPAD + icq] = gw[(oc0 + oc) * 576 + half * 288 + icq];
        }
        __syncthreads();
        const float* wrow = sW + oc_l * WPAD;
#pragma unroll 2
        for (int ic = 0; ic < 32; ic++) {
            const float* ip = sIn + (half * 32 + ic) * CPAD;
            float f[3][8];
#pragma unroll
            for (int r = 0; r < 3; r++) {
                int yy = y + r - 1;
                if (yy >= 0 && yy < 8) {
                    float4 v0 = *(const float4*)(ip + yy * 12);
                    float4 v1 = *(const float4*)(ip + yy * 12 + 4);
                    f[r][0] = v0.x; f[r][1] = v0.y; f[r][2] = v0.z; f[r][3] = v0.w;
                    f[r][4] = v1.x; f[r][5] = v1.y; f[r][6] = v1.z; f[r][7] = v1.w;
                } else {
#pragma unroll
                    for (int q = 0; q < 8; q++) f[r][q] = 0.f;
                }
            }
            const float* wp = wrow + ic * 9;
#pragma unroll
            for (int r = 0; r < 3; r++) {
                float w0 = wp[r * 3], w1 = wp[r * 3 + 1], w2 = wp[r * 3 + 2];
                acc[0] += w1 * f[r][0] + w2 * f[r][1];
#pragma unroll
                for (int j = 1; j < 7; j++)
                    acc[j] += w0 * f[r][j - 1] + w1 * f[r][j] + w2 * f[r][j + 1];
                acc[7] += w0 * f[r][6] + w1 * f[r][7];
            }
        }
    }
}

// ============== attention body (128 threads, block-uniform call) =============
__device__ void attention_body(int b, const float* __restrict__ fc1,
                               const float* __restrict__ fc2,
                               const float* __restrict__ att_b, int t0,
                               float* sIn, float* sW) {
    float* s_ah = sIn;            // 4096
    float* s_mean = sIn + 4096;   // 512
    float* s_max = sIn + 4608;    // 512
    float* sh = sW;               // 64
    float* se = sW + 64;          // 512
    int tid = threadIdx.x;
    int warp = tid >> 5, lane = tid & 31;

    __syncthreads();
    if (!t0) {
        for (int i = tid; i < 4096; i += 128) s_ah[i] = __ldcg(&g_ah[b * 4096 + i]);
    }
    __syncthreads();

#pragma unroll 4
    for (int q = 0; q < 128; q++) {
        int p = warp * 128 + q;
        int t = p >> 6, k = p & 63;
        const float* av = g_attv + ((b * T_ + t) * K_ + k) * 64;
        float a0, a1;
        if (t0) {
            float bk = att_b[k];
            a0 = __ldcg(&av[lane]) + bk;
            a1 = __ldcg(&av[lane + 32]) + bk;
        } else {
            a0 = __ldcg(&av[lane]) + s_ah[k * 64 + lane];
            a1 = __ldcg(&av[lane + 32]) + s_ah[k * 64 + lane + 32];
        }
        float v0 = fmaxf(a0, 0.f), v1 = fmaxf(a1, 0.f);
        float sum = v0 + v1;
        float mx = fmaxf(v0, v1);
#pragma unroll
        for (int o = 16; o; o >>= 1) {
            sum += __shfl_xor_sync(0xffffffffu, sum, o);
            mx = fmaxf(mx, __shfl_xor_sync(0xffffffffu, mx, o));
        }
        if (lane == 0) {
            s_mean[p] = sum * (1.f / 64.f);
            s_max[p] = mx;
        }
    }
    __syncthreads();

#pragma unroll
    for (int q = 0; q < 16; q++) {
        int dd = q * 4 + warp;
        const float* src = (dd < 32) ? s_mean : s_max;
        const float* wrow = fc1 + (dd & 31) * 512;
        float sum = 0.f;
        for (int i = lane; i < 512; i += 32) sum += src[i] * wrow[i];
#pragma unroll
        for (int o = 16; o; o >>= 1) sum += __shfl_xor_sync(0xffffffffu, sum, o);
        if (lane == 0) sh[dd] = fmaxf(sum, 0.f);
    }
    __syncthreads();

#pragma unroll
    for (int rep = 0; rep < 4; rep++) {
        int o = tid + rep * 128;
        const float* w2 = fc2 + o * 32;
        float v = 0.f;
#pragma unroll
        for (int j = 0; j < 32; j++) v += w2[j] * (sh[j] + sh[j + 32]);
        se[o] = expf(tanhf(v));
    }
    __syncthreads();

    if (tid < 64) {
        float den = 0.f;
#pragma unroll
        for (int t = 0; t < T_; t++) den += se[t * 64 + tid];
        if (den == 0.f) den = 1.f;
        float inv = 1.f / den;
#pragma unroll
        for (int t = 0; t < T_; t++) se[t * 64 + tid] *= inv;
    }
    __syncthreads();

#pragma unroll
    for (int ii = 0; ii < 8; ii++) {
        int idx4 = tid + ii * 128;
        int k = idx4 >> 4;
        float4 a = {0.f, 0.f, 0.f, 0.f};
#pragma unroll
        for (int t = 0; t < T_; t++) {
            float al = se[t * 64 + k];
            float4 v = *(const float4*)&g_wxpb[(b * T_ + t) * 4096 + idx4 * 4];
            a.x += al * v.x; a.y += al * v.y; a.z += al * v.z; a.w += al * v.w;
        }
        *(float4*)&g_wxt0[b * 4096 + idx4 * 4] = a;
    }
    __syncthreads();
}

// ============== persistent recurrence mega-kernel =============================
__global__ void __launch_bounds__(128, 3) recurrence_kernel(
    const float* __restrict__ att_x,
    const float* __restrict__ att_h_w, const float* __restrict__ att_b,
    const float* __restrict__ U_z, const float* __restrict__ U_r,
    const float* __restrict__ U_h,
    const float* __restrict__ share_w, const float* __restrict__ share_b,
    const float* __restrict__ fc1, const float* __restrict__ fc2) {
    __shared__ float sIn[64 * CPAD];   // 24576 B
    __shared__ float sW[16 * WPAD];    // 18688 B
    int bid = blockIdx.x;
    int tid = threadIdx.x;
    int n = bid / 12, r12 = bid % 12, which = r12 >> 2, ocg = r12 & 3;
    int y = tid & 7, oc_l = tid >> 3;

    // ---- Phase P: attv = conv(wxpb, att_x), 1024 tasks ----
    for (int task = bid; task < 1024; task += RGRID) {
        int pn = task >> 2, poc = (task & 3) * 16;
        float acc[8];
        conv3x3_v2(g_wxpb + pn * 4096, att_x, poc, sIn, sW, acc);
        float* o = g_attv + pn * 4096 + (poc + oc_l) * 64 + y * 8;
#pragma unroll
        for (int j = 0; j < 8; j++) o[j] = acc[j];
    }
    gbar();

    for (int t = 0; t < T_; t++) {
        // ---- Phase A: trio convs on h ----
        if (t > 0) {
            const float* w = (which == 0) ? att_h_w : (which == 1) ? U_z : U_r;
            float* outp = (which == 0) ? g_ah : (which == 1) ? g_uz : g_ur;
            float acc[8];
            conv3x3_v2(g_h + n * 4096, w, ocg * 16, sIn, sW, acc);
            int oc = ocg * 16 + oc_l;
            float bv = (which == 0) ? att_b[oc] : 0.f;
            float* o = outp + n * 4096 + oc * 64 + y * 8;
#pragma unroll
            for (int j = 0; j < 8; j++) o[j] = acc[j] + bv;
            gbar();
        }

        // ---- Phase B: attention (32 blocks) ----
        if (bid < B_) attention_body(bid, fc1, fc2, att_b, t == 0, sIn, sW);
        gbar();

        // ---- Phase C: share conv + gates (which==1, 128 blocks) ----
        if (which == 1) {
            float acc[8];
            conv3x3_v2(g_wxt0 + n * 4096, share_w, ocg * 16, sIn, sW, acc);
            int oc = ocg * 16 + oc_l;
            float bv = share_b[oc];
            int e = n * 4096 + oc * 64 + y * 8;
#pragma unroll
            for (int j = 0; j < 8; j++) {
                float wxt = acc[j] + bv;
                float z;
                if (t == 0) {
                    z = sigmoidf_(wxt);
                } else {
                    z = sigmoidf_(wxt + __ldcg(&g_uz[e + j]));
                    float r = sigmoidf_(wxt + __ldcg(&g_ur[e + j]));
                    g_rh[e + j] = r * __ldcg(&g_h[e + j]);
                }
                g_wxtb[e + j] = wxt;
                g_zb[e + j] = z;
            }
        }
        gbar();

        // ---- Phase D: final conv + GRU update (which==2, 128 blocks) ----
        if (which == 2) {
            float acc[8];
            if (t > 0) {
                conv3x3_v2(g_rh + n * 4096, U_h, ocg * 16, sIn, sW, acc);
            } else {
#pragma unroll
                for (int j = 0; j < 8; j++) acc[j] = 0.f;
            }
            int oc = ocg * 16 + oc_l;
            int e = n * 4096 + oc * 64 + y * 8;
            float* hsp = g_hs + ((t * B_ + n) * K_ + oc) * 64 + y * 8;
#pragma unroll
            for (int j = 0; j < 8; j++) {
                float hh = tanhf(__ldcg(&g_wxtb[e + j]) + acc[j]);
                float z = __ldcg(&g_zb[e + j]);
                float hprev = (t > 0) ? __ldcg(&g_h[e + j]) : 0.f;
                float hn = (1.f - z) * hh + z * hprev;
                g_h[e + j] = hn;
                hsp[j] = hn;
            }
        }
        gbar();
    }
}

// ---------------- VLAD GEMM (+ fused a_sum) ----------------
__global__ void __launch_bounds__(256) vlad_gemm(const float* __restrict__ centers) {
    int b = blockIdx.y;
    int d0 = blockIdx.x * 64;
    __shared__ float As[16][64];
    __shared__ float Bs[16][64];
    int tid = threadIdx.x, tx = tid & 15, ty = tid >> 4;
    float acc[4][4];
    float asacc[4] = {0.f, 0.f, 0.f, 0.f};
#pragma unroll
    for (int i = 0; i < 4; i++)
#pragma unroll
        for (int j = 0; j < 4; j++) acc[i][j] = 0.f;

    for (int ts0 = 0; ts0 < 512; ts0 += 16) {
        int t = ts0 >> 6, s0 = ts0 & 63;
        const float* hsb = g_hs + ((t * B_ + b) * K_) * 64 + s0;
        const float* xtb = g_xtT + (size_t)(b * T_ + t) * (HW_ * D_) + s0 * D_ + d0;
#pragma unroll
        for (int i = tid; i < 1024; i += 256) {
            int k = i >> 4, kk = i & 15;
            As[kk][k] = hsb[k * 64 + kk];
        }
#pragma unroll
        for (int i = tid; i < 1024; i += 256) {
            int kk = i >> 6, dd = i & 63;
            Bs[kk][dd] = xtb[kk * D_ + dd];
        }
        __syncthreads();
#pragma unroll
        for (int i = 0; i < 4; i++) asacc[i] += As[tx][ty * 4 + i];
#pragma unroll
        for (int kk = 0; kk < 16; kk++) {
            float a[4], bb[4];
#pragma unroll
            for (int i = 0; i < 4; i++) a[i] = As[kk][ty * 4 + i];
#pragma unroll
            for (int j = 0; j < 4; j++) bb[j] = Bs[kk][tx * 4 + j];
#pragma unroll
            for (int i = 0; i < 4; i++)
#pragma unroll
                for (int j = 0; j < 4; j++) acc[i][j] += a[i] * bb[j];
        }
        __syncthreads();
    }
#pragma unroll
    for (int o = 1; o < 16; o <<= 1)
#pragma unroll
        for (int i = 0; i < 4; i++)
            asacc[i] += __shfl_xor_sync(0xffffffffu, asacc[i], o);
#pragma unroll
    for (int i = 0; i < 4; i++) {
        int k = ty * 4 + i;
        float as = asacc[i];
#pragma unroll
        for (int j = 0; j < 4; j++) {
            int d = d0 + tx * 4 + j;
            g_vlad[b * (K_ * D_) + k * D_ + d] = acc[i][j] - as * centers[k * D_ + d];
        }
    }
}

// ---------------- two-level normalization ----------------
__global__ void __launch_bounds__(256) norm_kernel(float* __restrict__ out) {
    int b = blockIdx.x, tid = threadIdx.x;
    int warp = tid >> 5, lane = tid & 31;
    __shared__ float sss[64];
    __shared__ float sinv[64];
    __shared__ float sbinv;
    const float* v = g_vlad + b * (K_ * D_);
#pragma unroll
    for (int q = 0; q < 8; q++) {
        int k = warp * 8 + q;
        const float* row = v + k * D_;
        float ss = 0.f;
        for (int i = lane; i < D_; i += 32) { float x = row[i]; ss += x * x; }
#pragma unroll
        for (int o = 16; o; o >>= 1) ss += __shfl_xor_sync(0xffffffffu, ss, o);
        if (lane == 0) sss[k] = ss;
    }
    __syncthreads();
    if (tid < 64) sinv[tid] = 1.f / fmaxf(sqrtf(sss[tid]), 1e-12f);
    __syncthreads();
    if (tid == 0) {
        float tot = 0.f;
        for (int k = 0; k < 64; k++) tot += sss[k] * sinv[k] * sinv[k];
        sbinv = 1.f / fmaxf(sqrtf(tot), 1e-12f);
    }
    __syncthreads();
    float bi = sbinv;
    for (int i = tid; i < K_ * D_; i += 256)
        out[b * (K_ * D_) + i] = v[i] * sinv[i >> 9] * bi;
}

// ---------------- launcher ----------------
extern "C" void kernel_launch(void* const* d_in, const int* in_sizes, int n_in,
                              void* d_out, int out_size) {
    const float* x       = (const float*)d_in[0];
    const float* redu_w  = (const float*)d_in[1];
    const float* redu_b  = (const float*)d_in[2];
    const float* w_x     = (const float*)d_in[3];
    const float* att_x   = (const float*)d_in[4];
    const float* att_h_w = (const float*)d_in[5];
    const float* att_b   = (const float*)d_in[6];
    const float* share_w = (const float*)d_in[7];
    const float* share_b = (const float*)d_in[8];
    const float* U_r     = (const float*)d_in[9];
    const float* U_z     = (const float*)d_in[10];
    const float* U_h     = (const float*)d_in[11];
    const float* centers = (const float*)d_in[12];
    const float* fc1_w   = (const float*)d_in[13];
    const float* fc2_w   = (const float*)d_in[14];
    float* out = (float*)d_out;

    cudaFuncSetAttribute(gemm_redu_mma, cudaFuncAttributeMaxDynamicSharedMemorySize,
                         GSMEM);

    convert_w<<<(640 * CIN_ + 1023) / 1024, 1024>>>(redu_w);
    wxw_kernel<<<96, 256>>>(redu_w, redu_b, w_x);
    transpose_x<<<dim3(24, 256), 256>>>(x);
    gemm_redu_mma<<<dim3(128, 5), 256, GSMEM>>>();

    recurrence_kernel<<<RGRID, 128>>>(att_x, att_h_w, att_b, U_z, U_r, U_h,
                                      share_w, share_b, fc1_w, fc2_w);

    vlad_gemm<<<dim3(8, B_), 256>>>(centers);
    norm_kernel<<<B_, 256>>>(out);
}

// round 7
// speedup vs baseline: 1.0838x; 1.0838x over previous
#include <cuda_runtime.h>
#include <cuda_fp16.h>
#include <math.h>
#include <stdint.h>

#define B_ 32
#define T_ 8
#define K_ 64
#define D_ 512
#define CIN_ 1536
#define HW_ 64
#define NT_ 256

// ---------------- scratch (device globals; no allocation) ----------------
__device__ float g_xtT[NT_ * HW_ * D_];   // (n, s, d)
__device__ __half g_xh[(size_t)NT_ * HW_ * CIN_];
__device__ __half g_wh[640 * CIN_];
__device__ float g_biasx[640];
__device__ float g_wxpb[NT_ * K_ * HW_];
__device__ float g_attv[NT_ * K_ * HW_];
__device__ float g_hs [T_ * B_ * K_ * HW_];
__device__ float g_h   [B_ * K_ * HW_];
__device__ float g_ah  [B_ * K_ * HW_];
__device__ float g_uz  [B_ * K_ * HW_];
__device__ float g_ur  [B_ * K_ * HW_];
__device__ float g_wxt0[B_ * K_ * HW_];
__device__ float g_wxtb[B_ * K_ * HW_];
__device__ float g_zb  [B_ * K_ * HW_];
__device__ float g_rh  [B_ * K_ * HW_];
__device__ float g_mean[B_ * 512];
__device__ float g_maxv[B_ * 512];
__device__ float g_alph[B_ * 512];
__device__ float g_vlad[B_ * K_ * D_];
// per-b barrier state, padded to 128B lines
__device__ unsigned g_bcnt[B_ * 32];
__device__ unsigned g_bgen[B_ * 32];

__device__ __forceinline__ float sigmoidf_(float x) { return 1.f / (1.f + expf(-x)); }
__device__ __forceinline__ uint32_t smem_to_u32(const void* p) {
    uint32_t a;
    asm("{ .reg .u64 t; cvta.to.shared.u64 t, %1; cvt.u32.u64 %0, t; }"
        : "=r"(a) : "l"(p));
    return a;
}

// ---------------- per-b group barrier (12 arrivals) ----------------
__device__ __forceinline__ void gbar_b(int b) {
    __syncthreads();
    if (threadIdx.x == 0) {
        __threadfence();
        unsigned* cnt = &g_bcnt[b * 32];
        unsigned* gen = &g_bgen[b * 32];
        unsigned g = atomicAdd(gen, 0u);
        unsigned t = atomicAdd(cnt, 1u);
        if (t == 11u) {
            atomicExch(cnt, 0u);
            __threadfence();
            atomicExch(gen, g + 1u);
        } else {
            volatile unsigned* vg = gen;
            while (*vg == g) { __nanosleep(32); }
            __threadfence();
        }
    }
    __syncthreads();
}

// ---------------- convert W to fp16 + zero pad rows 576-639 ----------------
__global__ void convert_w(const float* __restrict__ W) {
    int i = blockIdx.x * 1024 + threadIdx.x;
    if (i >= 640 * CIN_) return;
    int d = i / CIN_;
    if (d < 512) g_wh[i] = __float2half(W[i]);
    else if (d >= 576) g_wh[i] = __float2half(0.f);
}

// ---------------- wxW = w_x @ W (fp16 rows 512-575) + bias vector ----------
__global__ void __launch_bounds__(256) wxw_kernel(const float* __restrict__ redu_w,
                                                  const float* __restrict__ redu_b,
                                                  const float* __restrict__ wx) {
    __shared__ float sW[128 * 16];
    __shared__ float sX[64 * 128];
    int tid = threadIdx.x;
    int c0 = blockIdx.x * 16;
    int c_l = tid & 15, kq = tid >> 4;
    float acc[4] = {0.f, 0.f, 0.f, 0.f};
    for (int dc = 0; dc < 4; dc++) {
        __syncthreads();
        for (int i = tid; i < 2048; i += 256) {
            int dd = i >> 4, c = i & 15;
            sW[i] = redu_w[(size_t)(dc * 128 + dd) * CIN_ + c0 + c];
        }
        for (int i = tid; i < 8192; i += 256) {
            int k = i >> 7, dd = i & 127;
            sX[i] = wx[k * 512 + dc * 128 + dd];
        }
        __syncthreads();
        for (int dd = 0; dd < 128; dd++) {
            float wv = sW[dd * 16 + c_l];
#pragma unroll
            for (int i = 0; i < 4; i++)
                acc[i] += sX[(kq * 4 + i) * 128 + dd] * wv;
        }
    }
#pragma unroll
    for (int i = 0; i < 4; i++)
        g_wh[(size_t)(512 + kq * 4 + i) * CIN_ + c0 + c_l] = __float2half(acc[i]);

    if (blockIdx.x == 0) {
        if (tid < 256) {
            g_biasx[tid] = redu_b[tid];
            g_biasx[tid + 256] = redu_b[tid + 256];
        }
        if (tid < 64) {
            float s = 0.f;
            for (int d = 0; d < 512; d++) s += wx[tid * 512 + d] * redu_b[d];
            g_biasx[512 + tid] = s;
            g_biasx[576 + tid] = 0.f;
        }
    }
}

// ---------------- transpose x -> fp16 K-major ----------------
__global__ void __launch_bounds__(256) transpose_x(const float* __restrict__ x) {
    __shared__ float sm[64 * 65];
    int n = blockIdx.y, c0 = blockIdx.x * 64;
    const float* src = x + ((size_t)n * CIN_ + c0) * 64;
    for (int i = threadIdx.x; i < 4096; i += 256) {
        int ci = i >> 6, s = i & 63;
        sm[ci * 65 + s] = src[i];
    }
    __syncthreads();
#pragma unroll
    for (int rep = 0; rep < 8; rep++) {
        int idx = rep * 256 + threadIdx.x;
        int s = idx >> 5, cp = idx & 31, ci = cp * 2;
        __half2 h = __floats2half2_rn(sm[ci * 65 + s], sm[(ci + 1) * 65 + s]);
        *(__half2*)(g_xh + ((size_t)(n * 64 + s)) * CIN_ + c0 + ci) = h;
    }
}

// ============== HMMA GEMM, 3-stage cp.async pipeline ========================
#define EPAD 67
#define NCH 48
#define STG 20480
#define GSMEM (3 * STG)

__device__ __forceinline__ void mma16816(float* c, const uint32_t* a, const uint32_t* b) {
    asm volatile(
        "mma.sync.aligned.m16n8k16.row.col.f32.f16.f16.f32 "
        "{%0,%1,%2,%3}, {%4,%5,%6,%7}, {%8,%9}, {%0,%1,%2,%3};"
        : "+f"(c[0]), "+f"(c[1]), "+f"(c[2]), "+f"(c[3])
        : "r"(a[0]), "r"(a[1]), "r"(a[2]), "r"(a[3]), "r"(b[0]), "r"(b[1]));
}
#define LDSM4(r0, r1, r2, r3, addr) \
    asm volatile("ldmatrix.sync.aligned.m8n8.x4.shared.b16 {%0,%1,%2,%3}, [%4];" \
                 : "=r"(r0), "=r"(r1), "=r"(r2), "=r"(r3) : "r"(addr))
#define CPASYNC16(saddr, gptr) \
    asm volatile("cp.async.cg.shared.global [%0], [%1], 16;" :: "r"(saddr), "l"(gptr))
#define CPCOMMIT() asm volatile("cp.async.commit_group;")
#define CPWAIT(n)  asm volatile("cp.async.wait_group %0;" :: "n"(n))

__global__ void __launch_bounds__(256) gemm_redu_mma() {
    extern __shared__ __align__(16) char sbuf[];
    float* sEp = (float*)sbuf;
    uint32_t sb = smem_to_u32(sbuf);

    int tid = threadIdx.x;
    int wid = tid >> 5, lane = tid & 31;
    int warp_m = wid >> 2, warp_n = wid & 3;
    int moff = warp_m * 64, noff = warp_n * 32;
    int m0 = blockIdx.x * 128, n0 = blockIdx.y * 128;
    int lr = lane >> 2, lc = (lane & 3) * 2;

    float acc[4][4][4];
#pragma unroll
    for (int i = 0; i < 4; i++)
#pragma unroll
        for (int j = 0; j < 4; j++)
#pragma unroll
            for (int q = 0; q < 4; q++) acc[i][j][q] = 0.f;

    int lane16 = lane & 15, lanehi = lane >> 4;
    uint32_t aBase = sb + (uint32_t)((moff + lane16) * 80 + lanehi * 16);
    int bgrp = lane >> 3;
    int brow = (lane & 7) + ((bgrp >> 1) << 3);
    int bcol = (bgrp & 1) << 3;
    uint32_t bBase = sb + 10240 + (uint32_t)((noff + brow) * 80 + bcol * 2);

    auto load_chunk = [&](int st, int ch) {
        int k0 = ch * 32;
        uint32_t abuf = sb + st * STG, bbuf = abuf + 10240;
#pragma unroll
        for (int i = tid; i < 512; i += 256) {
            int r = i >> 2, c = i & 3;
            CPASYNC16(abuf + (uint32_t)(r * 80 + c * 16),
                      g_xh + (size_t)(m0 + r) * CIN_ + k0 + c * 8);
            CPASYNC16(bbuf + (uint32_t)(r * 80 + c * 16),
                      g_wh + (size_t)(n0 + r) * CIN_ + k0 + c * 8);
        }
    };

    load_chunk(0, 0);
    CPCOMMIT();
    load_chunk(1, 1);
    CPCOMMIT();

#pragma unroll 1
    for (int ch = 0; ch < NCH; ch++) {
        if (ch < NCH - 1) CPWAIT(1); else CPWAIT(0);
        __syncthreads();
        if (ch + 2 < NCH) {
            load_chunk((ch + 2) % 3, ch + 2);
            CPCOMMIT();
        }
        uint32_t stoff = (uint32_t)((ch % 3) * STG);
        uint32_t af[2][4][4], bf[2][4][2];
#pragma unroll
        for (int ks = 0; ks < 2; ks++) {
#pragma unroll
            for (int mf = 0; mf < 4; mf++)
                LDSM4(af[ks][mf][0], af[ks][mf][1], af[ks][mf][2], af[ks][mf][3],
                      aBase + stoff + (uint32_t)(mf * 16 * 80 + ks * 32));
#pragma unroll
            for (int nfp = 0; nfp < 2; nfp++)
                LDSM4(bf[ks][2 * nfp][0], bf[ks][2 * nfp][1],
                      bf[ks][2 * nfp + 1][0], bf[ks][2 * nfp + 1][1],
                      bBase + stoff + (uint32_t)(nfp * 16 * 80 + ks * 32));
        }
#pragma unroll
        for (int ks = 0; ks < 2; ks++)
#pragma unroll
            for (int mf = 0; mf < 4; mf++)
#pragma unroll
                for (int nf = 0; nf < 4; nf++)
                    mma16816(acc[mf][nf], af[ks][mf], bf[ks][nf]);
    }

    if (n0 < 512) {
        // xtT-only epilogue, two 64-d slabs through smem
#pragma unroll 1
        for (int slab = 0; slab < 2; slab++) {
            __syncthreads();
            if ((warp_n >> 1) == slab) {
                int ncol = (warp_n & 1) * 32;
#pragma unroll
                for (int mf = 0; mf < 4; mf++) {
                    int row = moff + mf * 16 + lr;
#pragma unroll
                    for (int nf = 0; nf < 4; nf++) {
                        int col = ncol + nf * 8 + lc;
                        sEp[row * EPAD + col]           = acc[mf][nf][0];
                        sEp[row * EPAD + col + 1]       = acc[mf][nf][1];
                        sEp[(row + 8) * EPAD + col]     = acc[mf][nf][2];
                        sEp[(row + 8) * EPAD + col + 1] = acc[mf][nf][3];
                    }
                }
            }
            __syncthreads();
            int dbase = n0 + slab * 64;
#pragma unroll
            for (int idx = tid; idx < 8192; idx += 256) {
                int dn = idx & 63, m = idx >> 6;
                int col = m0 + m, nn = col >> 6, ss = col & 63;
                int d = dbase + dn;
                g_xtT[(size_t)nn * (HW_ * D_) + ss * 512 + d] = sEp[m * EPAD + dn] + g_biasx[d];
            }
        }
    } else {
        __syncthreads();
        if ((warp_n >> 1) == 0) {
            int ncol = (warp_n & 1) * 32;
#pragma unroll
            for (int mf = 0; mf < 4; mf++) {
                int row = moff + mf * 16 + lr;
#pragma unroll
                for (int nf = 0; nf < 4; nf++) {
                    int col = ncol + nf * 8 + lc;
                    sEp[row * EPAD + col]           = acc[mf][nf][0];
                    sEp[row * EPAD + col + 1]       = acc[mf][nf][1];
                    sEp[(row + 8) * EPAD + col]     = acc[mf][nf][2];
                    sEp[(row + 8) * EPAD + col + 1] = acc[mf][nf][3];
                }
            }
        }
        __syncthreads();
#pragma unroll
        for (int idx = tid; idx < 8192; idx += 256) {
            int m = idx & 127, dn = idx >> 7;
            int col = m0 + m, nn = col >> 6, ss = col & 63;
            g_wxpb[nn * 4096 + dn * 64 + ss] = sEp[m * EPAD + dn] + g_biasx[512 + dn];
        }
    }
}

// ============== conv3x3 core (128 thr, 16 oc; LDCG selects input load path) ==
#define CPAD 96
#define WPAD 292

template <bool LDCG>
__device__ void conv3x3_v2(const float* __restrict__ gin,
                           const float* __restrict__ gw, int oc0,
                           float* sIn, float* sW, float acc[8]) {
    int tid = threadIdx.x;
    int y = tid & 7;
    int oc_l = tid >> 3;
    __syncthreads();   // protect smem reuse across phases
    for (int i = tid; i < 4096; i += 128) {
        int ic = i >> 6, yy = (i >> 3) & 7, xx = i & 7;
        float v = LDCG ? __ldcg(&gin[i]) : gin[i];
        sIn[ic * CPAD + yy * 12 + xx] = v;
    }
#pragma unroll
    for (int j = 0; j < 8; j++) acc[j] = 0.f;

#pragma unroll 1
    for (int half = 0; half < 2; half++) {
        __syncthreads();
        for (int i = tid; i < 4608; i += 128) {
            int oc = i / 288, icq = i - oc * 288;
            sW[oc * WPAD + icq] = gw[(oc0 + oc) * 576 + half * 288 + icq];
        }
        __syncthreads();
        const float* wrow = sW + oc_l * WPAD;
#pragma unroll 2
        for (int ic = 0; ic < 32; ic++) {
            const float* ip = sIn + (half * 32 + ic) * CPAD;
            float f[3][8];
#pragma unroll
            for (int r = 0; r < 3; r++) {
                int yy = y + r - 1;
                if (yy >= 0 && yy < 8) {
                    float4 v0 = *(const float4*)(ip + yy * 12);
                    float4 v1 = *(const float4*)(ip + yy * 12 + 4);
                    f[r][0] = v0.x; f[r][1] = v0.y; f[r][2] = v0.z; f[r][3] = v0.w;
                    f[r][4] = v1.x; f[r][5] = v1.y; f[r][6] = v1.z; f[r][7] = v1.w;
                } else {
#pragma unroll
                    for (int q = 0; q < 8; q++) f[r][q] = 0.f;
                }
            }
            const float* wp = wrow + ic * 9;
#pragma unroll
            for (int r = 0; r < 3; r++) {
                float w0 = wp[r * 3], w1 = wp[r * 3 + 1], w2 = wp[r * 3 + 2];
                acc[0] += w1 * f[r][0] + w2 * f[r][1];
#pragma unroll
                for (int j = 1; j < 7; j++)
                    acc[j] += w0 * f[r][j - 1] + w1 * f[r][j] + w2 * f[r][j + 1];
                acc[7] += w0 * f[r][6] + w1 * f[r][7];
            }
        }
    }
}

// ============== persistent recurrence, per-b groups of 12 CTAs ===============
__global__ void __launch_bounds__(128, 3) recurrence_kernel(
    const float* __restrict__ att_x,
    const float* __restrict__ att_h_w, const float* __restrict__ att_b,
    const float* __restrict__ U_z, const float* __restrict__ U_r,
    const float* __restrict__ U_h,
    const float* __restrict__ share_w, const float* __restrict__ share_b,
    const float* __restrict__ fc1, const float* __restrict__ fc2) {
    __shared__ float sIn[64 * CPAD];   // 24576 B
    __shared__ float sW[16 * WPAD];    // 18688 B
    int bid = blockIdx.x;
    int tid = threadIdx.x;
    int b = bid / 12, r = bid % 12;
    int y = tid & 7, oc_l = tid >> 3;
    int warp = tid >> 5, lane = tid & 31;

    // ---- Phase P: attv[b] = conv(wxpb[b,t], att_x), 32 tasks over 12 blocks --
    for (int task = r; task < 32; task += 12) {
        int t = task >> 2, poc = (task & 3) * 16;
        float acc[8];
        conv3x3_v2<false>(g_wxpb + (b * T_ + t) * 4096, att_x, poc, sIn, sW, acc);
        float* o = g_attv + (b * T_ + t) * 4096 + (poc + oc_l) * 64 + y * 8;
#pragma unroll
        for (int j = 0; j < 8; j++) o[j] = acc[j];
    }
    gbar_b(b);

    for (int tt = 0; tt < T_; tt++) {
        // ---- Phase A: trio convs on h (12 blocks) ----
        if (tt > 0) {
            int which = r >> 2, ocg = r & 3;
            const float* w = (which == 0) ? att_h_w : (which == 1) ? U_z : U_r;
            float* outp = (which == 0) ? g_ah : (which == 1) ? g_uz : g_ur;
            float acc[8];
            conv3x3_v2<true>(g_h + b * 4096, w, ocg * 16, sIn, sW, acc);
            int oc = ocg * 16 + oc_l;
            float bv = (which == 0) ? att_b[oc] : 0.f;
            float* o = outp + b * 4096 + oc * 64 + y * 8;
#pragma unroll
            for (int j = 0; j < 8; j++) o[j] = acc[j] + bv;
            gbar_b(b);
        }

        // ---- Phase B1: stats for t=r (8 blocks) ----
        if (r < 8) {
            float* s_ah = sIn;
            __syncthreads();
            if (tt > 0) {
                for (int i = tid; i < 4096; i += 128)
                    s_ah[i] = __ldcg(&g_ah[b * 4096 + i]);
            }
            __syncthreads();
#pragma unroll 1
            for (int kk = 0; kk < 16; kk++) {
                int k = warp * 16 + kk;
                const float* av = g_attv + ((b * T_ + r) * K_ + k) * 64;
                float add0, add1;
                if (tt == 0) {
                    float bk = att_b[k];
                    add0 = bk; add1 = bk;
                } else {
                    add0 = s_ah[k * 64 + lane];
                    add1 = s_ah[k * 64 + lane + 32];
                }
                float v0 = fmaxf(av[lane] + add0, 0.f);
                float v1 = fmaxf(av[lane + 32] + add1, 0.f);
                float sum = v0 + v1;
                float mx = fmaxf(v0, v1);
#pragma unroll
                for (int o = 16; o; o >>= 1) {
                    sum += __shfl_xor_sync(0xffffffffu, sum, o);
                    mx = fmaxf(mx, __shfl_xor_sync(0xffffffffu, mx, o));
                }
                if (lane == 0) {
                    g_mean[b * 512 + r * 64 + k] = sum * (1.f / 64.f);
                    g_maxv[b * 512 + r * 64 + k] = mx;
                }
            }
        }
        gbar_b(b);

        // ---- Phase B2: fc + tanh + softmax (1 block) ----
        if (r == 0) {
            float* sh = sW;
            float* se = sW + 64;
            __syncthreads();
#pragma unroll 1
            for (int q = 0; q < 16; q++) {
                int dd = warp * 16 + q;
                const float* src = (dd < 32) ? (g_mean + b * 512) : (g_maxv + b * 512);
                const float* wrow = fc1 + (dd & 31) * 512;
                float sum = 0.f;
                for (int i = lane; i < 512; i += 32)
                    sum += __ldcg(&src[i]) * wrow[i];
#pragma unroll
                for (int o = 16; o; o >>= 1) sum += __shfl_xor_sync(0xffffffffu, sum, o);
                if (lane == 0) sh[dd] = fmaxf(sum, 0.f);
            }
            __syncthreads();
#pragma unroll
            for (int rep = 0; rep < 4; rep++) {
                int o = tid + rep * 128;
                const float* w2 = fc2 + o * 32;
                float v = 0.f;
#pragma unroll
                for (int j = 0; j < 32; j++) v += w2[j] * (sh[j] + sh[j + 32]);
                se[o] = expf(tanhf(v));
            }
            __syncthreads();
            if (tid < 64) {
                float den = 0.f;
#pragma unroll
                for (int t = 0; t < T_; t++) den += se[t * 64 + tid];
                if (den == 0.f) den = 1.f;
                float inv = 1.f / den;
#pragma unroll
                for (int t = 0; t < T_; t++)
                    g_alph[b * 512 + t * 64 + tid] = se[t * 64 + tid] * inv;
            }
        }
        gbar_b(b);

        // ---- Phase B3: wxt0 (8 blocks) ----
        if (r < 8) {
            float* sa = sW;
            __syncthreads();
            for (int i = tid; i < 512; i += 128) sa[i] = __ldcg(&g_alph[b * 512 + i]);
            __syncthreads();
            int idx4 = r * 128 + tid;          // 0..1023
            int k = idx4 >> 4;
            float4 a = {0.f, 0.f, 0.f, 0.f};
#pragma unroll
            for (int t = 0; t < T_; t++) {
                float al = sa[t * 64 + k];
                float4 v = *(const float4*)&g_wxpb[(b * T_ + t) * 4096 + idx4 * 4];
                a.x += al * v.x; a.y += al * v.y; a.z += al * v.z; a.w += al * v.w;
            }
            *(float4*)&g_wxt0[b * 4096 + idx4 * 4] = a;
        }
        gbar_b(b);

        // ---- Phase C: share conv + gates (4 blocks) ----
        if (r < 4) {
            float acc[8];
            conv3x3_v2<true>(g_wxt0 + b * 4096, share_w, r * 16, sIn, sW, acc);
            int oc = r * 16 + oc_l;
            float bv = share_b[oc];
            int e = b * 4096 + oc * 64 + y * 8;
#pragma unroll
            for (int j = 0; j < 8; j++) {
                float wxt = acc[j] + bv;
                float z;
                if (tt == 0) {
                    z = sigmoidf_(wxt);
                } else {
                    z = sigmoidf_(wxt + __ldcg(&g_uz[e + j]));
                    float rr = sigmoidf_(wxt + __ldcg(&g_ur[e + j]));
                    g_rh[e + j] = rr * __ldcg(&g_h[e + j]);
                }
                g_wxtb[e + j] = wxt;
                g_zb[e + j] = z;
            }
        }
        gbar_b(b);

        // ---- Phase D: U_h conv + GRU update (4 blocks) ----
        if (r < 4) {
            float acc[8];
            if (tt > 0) {
                conv3x3_v2<true>(g_rh + b * 4096, U_h, r * 16, sIn, sW, acc);
            } else {
#pragma unroll
                for (int j = 0; j < 8; j++) acc[j] = 0.f;
            }
            int oc = r * 16 + oc_l;
            int e = b * 4096 + oc * 64 + y * 8;
            float* hsp = g_hs + ((tt * B_ + b) * K_ + oc) * 64 + y * 8;
#pragma unroll
            for (int j = 0; j < 8; j++) {
                float hh = tanhf(__ldcg(&g_wxtb[e + j]) + acc[j]);
                float z = __ldcg(&g_zb[e + j]);
                float hprev = (tt > 0) ? __ldcg(&g_h[e + j]) : 0.f;
                float hn = (1.f - z) * hh + z * hprev;
                g_h[e + j] = hn;
                hsp[j] = hn;
            }
        }
        gbar_b(b);
    }
}

// ---------------- VLAD GEMM (+ fused a_sum) ----------------
__global__ void __launch_bounds__(256) vlad_gemm(const float* __restrict__ centers) {
    int b = blockIdx.y;
    int d0 = blockIdx.x * 64;
    __shared__ float As[16][64];
    __shared__ float Bs[16][64];
    int tid = threadIdx.x, tx = tid & 15, ty = tid >> 4;
    float acc[4][4];
    float asacc[4] = {0.f, 0.f, 0.f, 0.f};
#pragma unroll
    for (int i = 0; i < 4; i++)
#pragma unroll
        for (int j = 0; j < 4; j++) acc[i][j] = 0.f;

    for (int ts0 = 0; ts0 < 512; ts0 += 16) {
        int t = ts0 >> 6, s0 = ts0 & 63;
        const float* hsb = g_hs + ((t * B_ + b) * K_) * 64 + s0;
        const float* xtb = g_xtT + (size_t)(b * T_ + t) * (HW_ * D_) + s0 * D_ + d0;
#pragma unroll
        for (int i = tid; i < 1024; i += 256) {
            int k = i >> 4, kk = i & 15;
            As[kk][k] = hsb[k * 64 + kk];
        }
#pragma unroll
        for (int i = tid; i < 1024; i += 256) {
            int kk = i >> 6, dd = i & 63;
            Bs[kk][dd] = xtb[kk * D_ + dd];
        }
        __syncthreads();
#pragma unroll
        for (int i = 0; i < 4; i++) asacc[i] += As[tx][ty * 4 + i];
#pragma unroll
        for (int kk = 0; kk < 16; kk++) {
            float a[4], bb[4];
#pragma unroll
            for (int i = 0; i < 4; i++) a[i] = As[kk][ty * 4 + i];
#pragma unroll
            for (int j = 0; j < 4; j++) bb[j] = Bs[kk][tx * 4 + j];
#pragma unroll
            for (int i = 0; i < 4; i++)
#pragma unroll
                for (int j = 0; j < 4; j++) acc[i][j] += a[i] * bb[j];
        }
        __syncthreads();
    }
#pragma unroll
    for (int o = 1; o < 16; o <<= 1)
#pragma unroll
        for (int i = 0; i < 4; i++)
            asacc[i] += __shfl_xor_sync(0xffffffffu, asacc[i], o);
#pragma unroll
    for (int i = 0; i < 4; i++) {
        int k = ty * 4 + i;
        float as = asacc[i];
#pragma unroll
        for (int j = 0; j < 4; j++) {
            int d = d0 + tx * 4 + j;
            g_vlad[b * (K_ * D_) + k * D_ + d] = acc[i][j] - as * centers[k * D_ + d];
        }
    }
}

// ---------------- two-level normalization ----------------
__global__ void __launch_bounds__(256) norm_kernel(float* __restrict__ out) {
    int b = blockIdx.x, tid = threadIdx.x;
    int warp = tid >> 5, lane = tid & 31;
    __shared__ float sss[64];
    __shared__ float sinv[64];
    __shared__ float sbinv;
    const float* v = g_vlad + b * (K_ * D_);
#pragma unroll
    for (int q = 0; q < 8; q++) {
        int k = warp * 8 + q;
        const float* row = v + k * D_;
        float ss = 0.f;
        for (int i = lane; i < D_; i += 32) { float x = row[i]; ss += x * x; }
#pragma unroll
        for (int o = 16; o; o >>= 1) ss += __shfl_xor_sync(0xffffffffu, ss, o);
        if (lane == 0) sss[k] = ss;
    }
    __syncthreads();
    if (tid < 64) sinv[tid] = 1.f / fmaxf(sqrtf(sss[tid]), 1e-12f);
    __syncthreads();
    if (tid == 0) {
        float tot = 0.f;
        for (int k = 0; k < 64; k++) tot += sss[k] * sinv[k] * sinv[k];
        sbinv = 1.f / fmaxf(sqrtf(tot), 1e-12f);
    }
    __syncthreads();
    float bi = sbinv;
    for (int i = tid; i < K_ * D_; i += 256)
        out[b * (K_ * D_) + i] = v[i] * sinv[i >> 9] * bi;
}

// ---------------- launcher ----------------
extern "C" void kernel_launch(void* const* d_in, const int* in_sizes, int n_in,
                              void* d_out, int out_size) {
    const float* x       = (const float*)d_in[0];
    const float* redu_w  = (const float*)d_in[1];
    const float* redu_b  = (const float*)d_in[2];
    const float* w_x     = (const float*)d_in[3];
    const float* att_x   = (const float*)d_in[4];
    const float* att_h_w = (const float*)d_in[5];
    const float* att_b   = (const float*)d_in[6];
    const float* share_w = (const float*)d_in[7];
    const float* share_b = (const float*)d_in[8];
    const float* U_r     = (const float*)d_in[9];
    const float* U_z     = (const float*)d_in[10];
    const float* U_h     = (const float*)d_in[11];
    const float* centers = (const float*)d_in[12];
    const float* fc1_w   = (const float*)d_in[13];
    const float* fc2_w   = (const float*)d_in[14];
    float* out = (float*)d_out;

    cudaFuncSetAttribute(gemm_redu_mma, cudaFuncAttributeMaxDynamicSharedMemorySize,
                         GSMEM);

    convert_w<<<(640 * CIN_ + 1023) / 1024, 1024>>>(redu_w);
    wxw_kernel<<<96, 256>>>(redu_w, redu_b, w_x);
    transpose_x<<<dim3(24, 256), 256>>>(x);
    gemm_redu_mma<<<dim3(128, 5), 256, GSMEM>>>();

    recurrence_kernel<<<B_ * 12, 128>>>(att_x, att_h_w, att_b, U_z, U_r, U_h,
                                        share_w, share_b, fc1_w, fc2_w);

    vlad_gemm<<<dim3(8, B_), 256>>>(centers);
    norm_kernel<<<B_, 256>>>(out);
}